// round 1
// baseline (speedup 1.0000x reference)
#include <cuda_runtime.h>
#include <math.h>

#define BATCH 128
#define HH 512
#define WW 512
#define HW (HH*WW)

#define TILE 128
#define KFUSE 5
#define RS (TILE + 2*KFUSE)      // 138
#define WKD (TILE + 2*(KFUSE-1)) // 136
#define SMEM_BYTES ((2*RS*RS + WKD*WKD)*4)

// ---- scratch (device globals: allocation-free per harness rules) ----
__device__ float g_RA[(size_t)BATCH*HW];
__device__ float g_RB[(size_t)BATCH*HW];
__device__ float g_walk[(size_t)BATCH*HW];
__device__ float g_keys[BATCH];
__device__ float g_door[BATCH];

// ---------------------------------------------------------------
// zero R buffer (float4 grid-stride)
__global__ void zero_kernel(float4* __restrict__ p, long long n4) {
    long long i = (long long)blockIdx.x*blockDim.x + threadIdx.x;
    long long stride = (long long)gridDim.x*blockDim.x;
    float4 z = make_float4(0.f,0.f,0.f,0.f);
    for (; i < n4; i += stride) p[i] = z;
}

// seed start cells, zero keys
__global__ void seed_kernel(const int* __restrict__ start, float* __restrict__ R) {
    int b = threadIdx.x;
    if (b < BATCH) {
        int r = start[2*b], c = start[2*b+1];
        R[(size_t)b*HW + (size_t)r*WW + c] = 1.0f;
        g_keys[b] = 0.0f;
    }
}

// per-batch door_pass = sigmoid(kg*(keys-1))
__global__ void door_kernel(const float* __restrict__ kg) {
    int b = threadIdx.x;
    if (b < BATCH) {
        float x = kg[0] * (g_keys[b] - 1.0f);
        g_door[b] = 1.0f / (1.0f + expf(-x));
    }
}

// walk = floor * (1 - locked + locked*door_pass)
__global__ void walk_kernel(const float4* __restrict__ fl,
                            const float4* __restrict__ lk,
                            float4* __restrict__ wk) {
    int b = blockIdx.y;
    float dp = g_door[b];
    size_t base = (size_t)b * (HW/4);
    int i = blockIdx.x*blockDim.x + threadIdx.x;
    int stride = gridDim.x*blockDim.x;
    for (; i < HW/4; i += stride) {
        float4 f = fl[base + i];
        float4 l = lk[base + i];
        float4 w;
        w.x = f.x * (1.0f - l.x + l.x*dp);
        w.y = f.y * (1.0f - l.y + l.y*dp);
        w.z = f.z * (1.0f - l.z + l.z*dp);
        w.w = f.w * (1.0f - l.w + l.w*dp);
        wk[base + i] = w;
    }
}

// fused 5-iteration Jacobi stencil: R_{t+5} from R_t, tile 128x128, halo 5
__global__ __launch_bounds__(512, 1)
void stencil_kernel(const float* __restrict__ Rin,
                    const float* __restrict__ walk,
                    float* __restrict__ Rout) {
    extern __shared__ float sm[];
    float* Rs0 = sm;                 // RS*RS
    float* Rs1 = sm + RS*RS;         // RS*RS
    float* Wk  = sm + 2*RS*RS;       // WKD*WKD

    const int b   = blockIdx.z;
    const int ty0 = blockIdx.y * TILE;
    const int tx0 = blockIdx.x * TILE;
    const float* Rb = Rin  + (size_t)b*HW;
    const float* Wb = walk + (size_t)b*HW;
    const int tid = threadIdx.x;

    // load R with halo K (zero-fill OOB)
    for (int idx = tid; idx < RS*RS; idx += 512) {
        int y = idx / RS, x = idx - y*RS;
        int gy = ty0 + y - KFUSE, gx = tx0 + x - KFUSE;
        float v = 0.0f;
        if ((unsigned)gy < HH && (unsigned)gx < WW) v = __ldg(Rb + (size_t)gy*WW + gx);
        Rs0[idx] = v;
    }
    // load walk with halo K-1 (zero-fill OOB -> OOB cells stay 0)
    for (int idx = tid; idx < WKD*WKD; idx += 512) {
        int y = idx / WKD, x = idx - y*WKD;
        int gy = ty0 + y - (KFUSE-1), gx = tx0 + x - (KFUSE-1);
        float v = 0.0f;
        if ((unsigned)gy < HH && (unsigned)gx < WW) v = __ldg(Wb + (size_t)gy*WW + gx);
        Wk[idx] = v;
    }
    __syncthreads();

    float* cur = Rs0;
    float* nxt = Rs1;
    #pragma unroll
    for (int it = 0; it < KFUSE; ++it) {
        const int off = it + 1;
        const int s   = RS - 2*off;           // 136,134,132,130,128 (compile-time after unroll)
        const int n   = s * s;
        for (int idx = tid; idx < n; idx += 512) {
            int q = idx / s;
            int y = q + off;
            int x = idx - q*s + off;
            int p = y*RS + x;
            float c    = cur[p];
            float nsum = cur[p-RS] + cur[p+RS] + cur[p-1] + cur[p+1];
            float w    = Wk[(y-1)*WKD + (x-1)];
            float v    = fmaf(nsum*0.25f, w, c);
            v = fminf(fmaxf(v, 0.0f), 1.0f);
            nxt[p] = v;
        }
        __syncthreads();
        float* t = cur; cur = nxt; nxt = t;
    }

    // store interior
    float* Ro = Rout + (size_t)b*HW;
    for (int idx = tid; idx < TILE*TILE; idx += 512) {
        int y = idx >> 7, x = idx & 127;
        Ro[(size_t)(ty0+y)*WW + (tx0+x)] = cur[(y+KFUSE)*RS + (x+KFUSE)];
    }
}

// keys[b] += sum(R*key_loc) over the batch plane (deterministic block reduce)
__global__ void reduce_kernel(const float* __restrict__ R,
                              const float* __restrict__ keyloc) {
    int b = blockIdx.x;
    const float4* r4 = (const float4*)(R      + (size_t)b*HW);
    const float4* k4 = (const float4*)(keyloc + (size_t)b*HW);
    float acc = 0.0f;
    for (int i = threadIdx.x; i < HW/4; i += blockDim.x) {
        float4 r = r4[i], k = k4[i];
        acc += r.x*k.x + r.y*k.y + r.z*k.z + r.w*k.w;
    }
    __shared__ float sred[256];
    sred[threadIdx.x] = acc;
    __syncthreads();
    for (int s = 128; s > 0; s >>= 1) {
        if (threadIdx.x < s) sred[threadIdx.x] += sred[threadIdx.x + s];
        __syncthreads();
    }
    if (threadIdx.x == 0) g_keys[b] += sred[0];
}

// out[b] = R[b, clip(goal_r), clip(goal_c)]
__global__ void gather_kernel(const float* __restrict__ R,
                              const int* __restrict__ goal,
                              float* __restrict__ out) {
    int b = threadIdx.x;
    if (b < BATCH) {
        int gr = min(max(goal[2*b],   0), HH-1);
        int gc = min(max(goal[2*b+1], 0), WW-1);
        out[b] = R[(size_t)b*HW + (size_t)gr*WW + gc];
    }
}

// ---------------------------------------------------------------
extern "C" void kernel_launch(void* const* d_in, const int* in_sizes, int n_in,
                              void* d_out, int out_size) {
    const float* floor_  = (const float*)d_in[0];
    const float* keyloc  = (const float*)d_in[1];
    const float* locked  = (const float*)d_in[2];
    const int*   start   = (const int*)  d_in[3];
    const int*   goal    = (const int*)  d_in[4];
    const float* keygate = (const float*)d_in[5];
    float* out = (float*)d_out;

    float *RA, *RB, *Wp;
    cudaGetSymbolAddress((void**)&RA, g_RA);
    cudaGetSymbolAddress((void**)&RB, g_RB);
    cudaGetSymbolAddress((void**)&Wp, g_walk);

    cudaFuncSetAttribute(stencil_kernel,
                         cudaFuncAttributeMaxDynamicSharedMemorySize, SMEM_BYTES);

    // init R = 0, seed starts, zero keys
    zero_kernel<<<4096, 256>>>((float4*)RA, (long long)BATCH*HW/4);
    seed_kernel<<<1, 128>>>(start, RA);

    float* cur = RA;
    float* oth = RB;
    for (int stage = 0; stage < 3; ++stage) {
        door_kernel<<<1, 128>>>(keygate);
        walk_kernel<<<dim3(32, BATCH), 256>>>((const float4*)floor_,
                                              (const float4*)locked,
                                              (float4*)Wp);
        for (int ss = 0; ss < 3; ++ss) {   // 3 super-steps x 5 fused iters = 15
            stencil_kernel<<<dim3(WW/TILE, HH/TILE, BATCH), 512, SMEM_BYTES>>>(cur, Wp, oth);
            float* t = cur; cur = oth; oth = t;
        }
        if (stage < 2)  // last stage's key update is dead code in the reference
            reduce_kernel<<<BATCH, 256>>>(cur, keyloc);
    }
    gather_kernel<<<1, 128>>>(cur, goal, out);
}

// round 2
// speedup vs baseline: 1.1131x; 1.1131x over previous
#include <cuda_runtime.h>
#include <math.h>

#define BATCH 128
#define HH 512
#define WW 512
#define HW (HH*WW)

#define TILE 128
#define KFUSE 5
#define RROWS (TILE + 2*KFUSE)   // 138
#define RSTRIDE 140              // padded to multiple of 4 for float4
#define VPR (RSTRIDE/4)          // 35 float4 per row
#define NVEC ((RROWS-2)*VPR)     // 136*35 = 4760 vec-points per iteration
#define SMEM_BYTES (3*RROWS*RSTRIDE*4)   // 231,840 B (opt-in)

#define NCHUNK 8                 // reduction chunks per batch

// ---- scratch (device globals: allocation-free per harness rules) ----
__device__ float g_RA[(size_t)BATCH*HW];
__device__ float g_RB[(size_t)BATCH*HW];
__device__ float g_walk[(size_t)BATCH*HW];
__device__ float g_keys[BATCH];
__device__ float g_door[BATCH];
__device__ float g_partial[BATCH*NCHUNK];

// ---------------------------------------------------------------
__global__ void zero_kernel(float4* __restrict__ p, long long n4) {
    long long i = (long long)blockIdx.x*blockDim.x + threadIdx.x;
    long long stride = (long long)gridDim.x*blockDim.x;
    float4 z = make_float4(0.f,0.f,0.f,0.f);
    for (; i < n4; i += stride) p[i] = z;
}

// seed start cells, zero keys + partials
__global__ void seed_kernel(const int* __restrict__ start, float* __restrict__ R) {
    int b = threadIdx.x;
    if (b < BATCH) {
        int r = start[2*b], c = start[2*b+1];
        R[(size_t)b*HW + (size_t)r*WW + c] = 1.0f;
        g_keys[b] = 0.0f;
        for (int j = 0; j < NCHUNK; ++j) g_partial[b*NCHUNK + j] = 0.0f;
    }
}

// keys += sum(partials); zero partials; door_pass = sigmoid(kg*(keys-1))
__global__ void door_kernel(const float* __restrict__ kg) {
    int b = threadIdx.x;
    if (b < BATCH) {
        float s = 0.0f;
        for (int j = 0; j < NCHUNK; ++j) {
            s += g_partial[b*NCHUNK + j];
            g_partial[b*NCHUNK + j] = 0.0f;
        }
        g_keys[b] += s;
        float x = kg[0] * (g_keys[b] - 1.0f);
        g_door[b] = 1.0f / (1.0f + expf(-x));
    }
}

// walk = floor * (1 - locked + locked*door_pass)
__global__ void walk_kernel(const float4* __restrict__ fl,
                            const float4* __restrict__ lk,
                            float4* __restrict__ wk) {
    int b = blockIdx.y;
    float dp = g_door[b];
    size_t base = (size_t)b * (HW/4);
    int i = blockIdx.x*blockDim.x + threadIdx.x;
    int stride = gridDim.x*blockDim.x;
    for (; i < HW/4; i += stride) {
        float4 f = fl[base + i];
        float4 l = lk[base + i];
        float4 w;
        w.x = f.x * (1.0f - l.x + l.x*dp);
        w.y = f.y * (1.0f - l.y + l.y*dp);
        w.z = f.z * (1.0f - l.z + l.z*dp);
        w.w = f.w * (1.0f - l.w + l.w*dp);
        wk[base + i] = w;
    }
}

// fused 5-iteration Jacobi stencil, float4 vectorized, uniform sweep region.
// Tile 128x128, halo 5, padded row stride 140 floats.
__global__ __launch_bounds__(1024, 1)
void stencil_kernel(const float* __restrict__ Rin,
                    const float* __restrict__ walk,
                    float* __restrict__ Rout) {
    extern __shared__ float sm[];
    float* Rs0 = sm;                       // RROWS*RSTRIDE
    float* Rs1 = sm + RROWS*RSTRIDE;
    float* Wk  = sm + 2*RROWS*RSTRIDE;

    const int b   = blockIdx.z;
    const int ty0 = blockIdx.y * TILE;
    const int tx0 = blockIdx.x * TILE;
    const float* Rb = Rin  + (size_t)b*HW;
    const float* Wb = walk + (size_t)b*HW;
    const int tid = threadIdx.x;

    // load R and walk with halo 5 into padded layout (zero-fill OOB / pad cols)
    for (int idx = tid; idx < RROWS*RSTRIDE; idx += 1024) {
        int y = idx / RSTRIDE, x = idx - y*RSTRIDE;
        int gy = ty0 + y - KFUSE, gx = tx0 + x - KFUSE;
        float r = 0.0f, w = 0.0f;
        if ((unsigned)gy < HH && (unsigned)gx < WW && x < RROWS) {
            size_t g = (size_t)gy*WW + gx;
            r = __ldg(Rb + g);
            w = __ldg(Wb + g);
        }
        Rs0[idx] = r;
        Wk[idx]  = w;
    }
    __syncthreads();

    const float4* __restrict__ W4 = (const float4*)Wk;
    float* cur = Rs0;
    float* nxt = Rs1;
    #pragma unroll
    for (int it = 0; it < KFUSE; ++it) {
        const float4* __restrict__ c4 = (const float4*)cur;
        float4* __restrict__ n4p = (float4*)nxt;
        for (int idx = tid; idx < NVEC; idx += 1024) {
            int q = idx / VPR;              // row - 1
            int y = q + 1;
            int v = idx - q*VPR;
            int pv = y*VPR + v;             // float4 index
            float4 C = c4[pv];
            float4 U = c4[pv - VPR];
            float4 D = c4[pv + VPR];
            float4 L = c4[pv - 1];          // junk wrap at v==0 row edge: outside validity
            float4 R = c4[pv + 1];
            float4 W = W4[pv];
            float4 o;
            float n0 = (U.x + D.x) + (L.w + C.y);
            float n1 = (U.y + D.y) + (C.x + C.z);
            float n2 = (U.z + D.z) + (C.y + C.w);
            float n3 = (U.w + D.w) + (C.z + R.x);
            o.x = fminf(fmaxf(fmaf(n0*0.25f, W.x, C.x), 0.0f), 1.0f);
            o.y = fminf(fmaxf(fmaf(n1*0.25f, W.y, C.y), 0.0f), 1.0f);
            o.z = fminf(fmaxf(fmaf(n2*0.25f, W.z, C.z), 0.0f), 1.0f);
            o.w = fminf(fmaxf(fmaf(n3*0.25f, W.w, C.w), 0.0f), 1.0f);
            n4p[pv] = o;
        }
        __syncthreads();
        float* t = cur; cur = nxt; nxt = t;
    }

    // store interior 128x128
    float* Ro = Rout + (size_t)b*HW;
    for (int idx = tid; idx < TILE*TILE; idx += 1024) {
        int y = idx >> 7, x = idx & 127;
        Ro[(size_t)(ty0+y)*WW + (tx0+x)] = cur[(y+KFUSE)*RSTRIDE + (x+KFUSE)];
    }
}

// partial[b][chunk] = sum(R*key_loc) over chunk (deterministic)
__global__ void reduce_kernel(const float* __restrict__ R,
                              const float* __restrict__ keyloc) {
    int b = blockIdx.y;
    int chunk = blockIdx.x;
    const int per = HW/4/NCHUNK;            // 8192 float4
    const float4* r4 = (const float4*)(R      + (size_t)b*HW) + chunk*per;
    const float4* k4 = (const float4*)(keyloc + (size_t)b*HW) + chunk*per;
    float acc = 0.0f;
    for (int i = threadIdx.x; i < per; i += blockDim.x) {
        float4 r = r4[i], k = k4[i];
        acc += (r.x*k.x + r.y*k.y) + (r.z*k.z + r.w*k.w);
    }
    __shared__ float sred[256];
    sred[threadIdx.x] = acc;
    __syncthreads();
    for (int s = 128; s > 0; s >>= 1) {
        if (threadIdx.x < s) sred[threadIdx.x] += sred[threadIdx.x + s];
        __syncthreads();
    }
    if (threadIdx.x == 0) g_partial[b*NCHUNK + chunk] = sred[0];
}

// out[b] = R[b, clip(goal_r), clip(goal_c)]
__global__ void gather_kernel(const float* __restrict__ R,
                              const int* __restrict__ goal,
                              float* __restrict__ out) {
    int b = threadIdx.x;
    if (b < BATCH) {
        int gr = min(max(goal[2*b],   0), HH-1);
        int gc = min(max(goal[2*b+1], 0), WW-1);
        out[b] = R[(size_t)b*HW + (size_t)gr*WW + gc];
    }
}

// ---------------------------------------------------------------
extern "C" void kernel_launch(void* const* d_in, const int* in_sizes, int n_in,
                              void* d_out, int out_size) {
    const float* floor_  = (const float*)d_in[0];
    const float* keyloc  = (const float*)d_in[1];
    const float* locked  = (const float*)d_in[2];
    const int*   start   = (const int*)  d_in[3];
    const int*   goal    = (const int*)  d_in[4];
    const float* keygate = (const float*)d_in[5];
    float* out = (float*)d_out;

    float *RA, *RB, *Wp;
    cudaGetSymbolAddress((void**)&RA, g_RA);
    cudaGetSymbolAddress((void**)&RB, g_RB);
    cudaGetSymbolAddress((void**)&Wp, g_walk);

    cudaFuncSetAttribute(stencil_kernel,
                         cudaFuncAttributeMaxDynamicSharedMemorySize, SMEM_BYTES);

    zero_kernel<<<4096, 256>>>((float4*)RA, (long long)BATCH*HW/4);
    seed_kernel<<<1, 128>>>(start, RA);

    float* cur = RA;
    float* oth = RB;
    for (int stage = 0; stage < 3; ++stage) {
        door_kernel<<<1, 128>>>(keygate);   // folds in previous stage's partial sums
        walk_kernel<<<dim3(32, BATCH), 256>>>((const float4*)floor_,
                                              (const float4*)locked,
                                              (float4*)Wp);
        for (int ss = 0; ss < 3; ++ss) {    // 3 super-steps x 5 fused iters = 15
            stencil_kernel<<<dim3(WW/TILE, HH/TILE, BATCH), 1024, SMEM_BYTES>>>(cur, Wp, oth);
            float* t = cur; cur = oth; oth = t;
        }
        if (stage < 2)                      // last stage's key update is dead code
            reduce_kernel<<<dim3(NCHUNK, BATCH), 256>>>(cur, keyloc);
    }
    gather_kernel<<<1, 128>>>(cur, goal, out);
}

// round 3
// speedup vs baseline: 1.2322x; 1.1070x over previous
#include <cuda_runtime.h>
#include <math.h>

#define BATCH 128
#define HH 512
#define WW 512
#define HW (HH*WW)

#define TILE 128
#define KFUSE 5
#define RROWS (TILE + 2*KFUSE)   // 138 rows (0..137)
#define RSTRIDE 140              // padded row stride (multiple of 4)
#define VPR (RSTRIDE/4)          // 35 float4 per row
#define SMEM_BYTES (3*RROWS*RSTRIDE*4)   // 231,840 B

#define NCHUNK 8                 // reduction chunks per batch

// ---- scratch (device globals: allocation-free per harness rules) ----
__device__ float g_RA[(size_t)BATCH*HW];
__device__ float g_RB[(size_t)BATCH*HW];
__device__ float g_walk[(size_t)BATCH*HW];
__device__ float g_keys[BATCH];
__device__ float g_door[BATCH];
__device__ float g_partial[BATCH*NCHUNK];

// ---------------------------------------------------------------
__global__ void zero_kernel(float4* __restrict__ p, long long n4) {
    long long i = (long long)blockIdx.x*blockDim.x + threadIdx.x;
    long long stride = (long long)gridDim.x*blockDim.x;
    float4 z = make_float4(0.f,0.f,0.f,0.f);
    for (; i < n4; i += stride) p[i] = z;
}

// seed start cells, zero keys + partials
__global__ void seed_kernel(const int* __restrict__ start, float* __restrict__ R) {
    int b = threadIdx.x;
    if (b < BATCH) {
        int r = start[2*b], c = start[2*b+1];
        R[(size_t)b*HW + (size_t)r*WW + c] = 1.0f;
        g_keys[b] = 0.0f;
        for (int j = 0; j < NCHUNK; ++j) g_partial[b*NCHUNK + j] = 0.0f;
    }
}

// keys += sum(partials); zero partials; door_pass = sigmoid(kg*(keys-1))
__global__ void door_kernel(const float* __restrict__ kg) {
    int b = threadIdx.x;
    if (b < BATCH) {
        float s = 0.0f;
        for (int j = 0; j < NCHUNK; ++j) {
            s += g_partial[b*NCHUNK + j];
            g_partial[b*NCHUNK + j] = 0.0f;
        }
        g_keys[b] += s;
        float x = kg[0] * (g_keys[b] - 1.0f);
        g_door[b] = 1.0f / (1.0f + expf(-x));
    }
}

// walk = 0.25 * floor * (1 - locked + locked*door_pass)   (0.25 folded in)
__global__ void walk_kernel(const float4* __restrict__ fl,
                            const float4* __restrict__ lk,
                            float4* __restrict__ wk) {
    int b = blockIdx.y;
    float dp = g_door[b];
    size_t base = (size_t)b * (HW/4);
    int i = blockIdx.x*blockDim.x + threadIdx.x;
    int stride = gridDim.x*blockDim.x;
    for (; i < HW/4; i += stride) {
        float4 f = fl[base + i];
        float4 l = lk[base + i];
        float4 w;
        w.x = 0.25f * f.x * (1.0f - l.x + l.x*dp);
        w.y = 0.25f * f.y * (1.0f - l.y + l.y*dp);
        w.z = 0.25f * f.z * (1.0f - l.z + l.z*dp);
        w.w = 0.25f * f.w * (1.0f - l.w + l.w*dp);
        wk[base + i] = w;
    }
}

// fused 5-iteration Jacobi stencil with vertical register walking + shuffles.
// Tile 128x128, halo 5, padded row stride 140 floats. Final iter streams to gmem.
__global__ __launch_bounds__(1024, 1)
void stencil_kernel(const float* __restrict__ Rin,
                    const float* __restrict__ walk,
                    float* __restrict__ Rout) {
    extern __shared__ float sm[];
    float* Rs0 = sm;                       // RROWS*RSTRIDE
    float* Rs1 = sm + RROWS*RSTRIDE;
    float* Wk  = sm + 2*RROWS*RSTRIDE;

    const int b   = blockIdx.z;
    const int ty0 = blockIdx.y * TILE;
    const int tx0 = blockIdx.x * TILE;
    const float* Rb = Rin  + (size_t)b*HW;
    const float* Wb = walk + (size_t)b*HW;
    const int tid  = threadIdx.x;
    const int lane = tid & 31;

    // load R and walk with halo 5 into identical padded layouts (zero-fill OOB)
    for (int idx = tid; idx < RROWS*RSTRIDE; idx += 1024) {
        int y = idx / RSTRIDE, x = idx - y*RSTRIDE;
        int gy = ty0 + y - KFUSE, gx = tx0 + x - KFUSE;
        float r = 0.0f, w = 0.0f;
        if ((unsigned)gy < HH && (unsigned)gx < WW && x < RROWS) {
            size_t g = (size_t)gy*WW + gx;
            r = __ldg(Rb + g);
            w = __ldg(Wb + g);
        }
        Rs0[idx] = r;
        Wk[idx]  = w;
    }
    // rows 0 and 137 of Rs1 are never written by the sweep; zero them so junk stays bounded
    if (tid < 2*RSTRIDE) {
        int y = (tid < RSTRIDE) ? 0 : (RROWS-1);
        Rs1[y*RSTRIDE + (tid % RSTRIDE)] = 0.0f;
    }
    __syncthreads();

    // thread -> (v = float4 column, g = row group of 5 rows)
    int v = tid % VPR;                // 0..34
    int g = tid / VPR;                // 0..29 (29 groups used)
    const bool act = (tid < 29*VPR);  // 1015 active
    if (!act) { v = VPR-1; g = 28; }
    const int y0 = 1 + g*5;           // sweep rows 1..136

    const float4* __restrict__ W4 = (const float4*)Wk;
    float* Ro = Rout + (size_t)b*HW;

    float* cur = Rs0;
    float* nxt = Rs1;
    #pragma unroll
    for (int it = 0; it < KFUSE; ++it) {
        const float4* __restrict__ c4 = (const float4*)cur;
        float4* __restrict__ n4p = (float4*)nxt;
        const bool last = (it == KFUSE-1);

        int yc0 = min(y0, 136);
        float4 U = c4[(yc0-1)*VPR + v];
        float4 C = c4[ yc0   *VPR + v];
        #pragma unroll
        for (int i = 0; i < 5; ++i) {
            const int yr = y0 + i;
            const int y  = min(yr, 136);
            float4 D = c4[(y+1)*VPR + v];
            float4 W = W4[y*VPR + v];
            float upw = __shfl_up_sync(0xffffffffu,  C.w, 1);
            float dnx = __shfl_down_sync(0xffffffffu, C.x, 1);
            if (lane == 0)  upw = (v > 0)     ? cur[y*RSTRIDE + v*4 - 1] : 0.0f;
            if (lane == 31) dnx = (v < VPR-1) ? cur[y*RSTRIDE + v*4 + 4] : 0.0f;
            float4 o;
            o.x = fminf(fmaf((U.x+D.x)+(upw+C.y), W.x, C.x), 1.0f);
            o.y = fminf(fmaf((U.y+D.y)+(C.x+C.z), W.y, C.y), 1.0f);
            o.z = fminf(fmaf((U.z+D.z)+(C.y+C.w), W.z, C.z), 1.0f);
            o.w = fminf(fmaf((U.w+D.w)+(C.z+dnx), W.w, C.w), 1.0f);
            if (!last) {
                if (act && yr <= 136) n4p[y*VPR + v] = o;
            } else {
                // stream interior (floats [5,133), rows [5,132]) straight to gmem
                if (act && yr >= KFUSE && yr <= 137-KFUSE) {
                    const int gy = ty0 + yr - KFUSE;
                    float* row = Ro + (size_t)gy*WW + tx0 - KFUSE;
                    const int xf = v*4;
                    #pragma unroll
                    for (int c = 0; c < 4; ++c) {
                        int x = xf + c;
                        if (x >= KFUSE && x < RROWS-KFUSE)
                            row[x] = (&o.x)[c];
                    }
                }
            }
            U = C; C = D;
        }
        __syncthreads();
        float* t = cur; cur = nxt; nxt = t;
    }
}

// partial[b][chunk] = sum(R*key_loc) over chunk (deterministic)
__global__ void reduce_kernel(const float* __restrict__ R,
                              const float* __restrict__ keyloc) {
    int b = blockIdx.y;
    int chunk = blockIdx.x;
    const int per = HW/4/NCHUNK;            // 8192 float4
    const float4* r4 = (const float4*)(R      + (size_t)b*HW) + chunk*per;
    const float4* k4 = (const float4*)(keyloc + (size_t)b*HW) + chunk*per;
    float acc = 0.0f;
    for (int i = threadIdx.x; i < per; i += blockDim.x) {
        float4 r = r4[i], k = k4[i];
        acc += (r.x*k.x + r.y*k.y) + (r.z*k.z + r.w*k.w);
    }
    __shared__ float sred[256];
    sred[threadIdx.x] = acc;
    __syncthreads();
    for (int s = 128; s > 0; s >>= 1) {
        if (threadIdx.x < s) sred[threadIdx.x] += sred[threadIdx.x + s];
        __syncthreads();
    }
    if (threadIdx.x == 0) g_partial[b*NCHUNK + chunk] = sred[0];
}

// out[b] = R[b, clip(goal_r), clip(goal_c)]
__global__ void gather_kernel(const float* __restrict__ R,
                              const int* __restrict__ goal,
                              float* __restrict__ out) {
    int b = threadIdx.x;
    if (b < BATCH) {
        int gr = min(max(goal[2*b],   0), HH-1);
        int gc = min(max(goal[2*b+1], 0), WW-1);
        out[b] = R[(size_t)b*HW + (size_t)gr*WW + gc];
    }
}

// ---------------------------------------------------------------
extern "C" void kernel_launch(void* const* d_in, const int* in_sizes, int n_in,
                              void* d_out, int out_size) {
    const float* floor_  = (const float*)d_in[0];
    const float* keyloc  = (const float*)d_in[1];
    const float* locked  = (const float*)d_in[2];
    const int*   start   = (const int*)  d_in[3];
    const int*   goal    = (const int*)  d_in[4];
    const float* keygate = (const float*)d_in[5];
    float* out = (float*)d_out;

    float *RA, *RB, *Wp;
    cudaGetSymbolAddress((void**)&RA, g_RA);
    cudaGetSymbolAddress((void**)&RB, g_RB);
    cudaGetSymbolAddress((void**)&Wp, g_walk);

    cudaFuncSetAttribute(stencil_kernel,
                         cudaFuncAttributeMaxDynamicSharedMemorySize, SMEM_BYTES);

    zero_kernel<<<4096, 256>>>((float4*)RA, (long long)BATCH*HW/4);
    seed_kernel<<<1, 128>>>(start, RA);

    float* cur = RA;
    float* oth = RB;
    for (int stage = 0; stage < 3; ++stage) {
        door_kernel<<<1, 128>>>(keygate);   // folds in previous stage's partial sums
        walk_kernel<<<dim3(32, BATCH), 256>>>((const float4*)floor_,
                                              (const float4*)locked,
                                              (float4*)Wp);
        for (int ss = 0; ss < 3; ++ss) {    // 3 super-steps x 5 fused iters = 15
            stencil_kernel<<<dim3(WW/TILE, HH/TILE, BATCH), 1024, SMEM_BYTES>>>(cur, Wp, oth);
            float* t = cur; cur = oth; oth = t;
        }
        if (stage < 2)                      // last stage's key update is dead code
            reduce_kernel<<<dim3(NCHUNK, BATCH), 256>>>(cur, keyloc);
    }
    gather_kernel<<<1, 128>>>(cur, goal, out);
}

// round 4
// speedup vs baseline: 1.9342x; 1.5697x over previous
#include <cuda_runtime.h>
#include <math.h>

#define BATCH 128
#define HH 512
#define WW 512
#define HW (HH*WW)
#define W4R (WW/4)               // 128 float4 per image row

#define TILE 64                  // 64x64 tiles
#define KFUSE 5
#define ROWS 74                  // tile + 2*5 halo rows (global ty0-5 .. ty0+68)
#define STR 80                   // padded col stride in floats (left halo 8, right pad)
#define VPRX (STR/4)             // 20 float4 per row
#define NG 12                    // row groups per tile
#define RPG 6                    // rows per group (12*6 = 72 sweep rows)
#define NCOL 18                  // active float4 columns v = 1..18
#define SMEM_BYTES (2*ROWS*STR*4)   // 47,360 B

#define NCHUNK 8                 // reduction chunks per batch

// ---- scratch (device globals: allocation-free per harness rules) ----
__device__ float g_RA[(size_t)BATCH*HW];
__device__ float g_RB[(size_t)BATCH*HW];
__device__ float g_walk[(size_t)BATCH*HW];
__device__ float g_keys[BATCH];
__device__ float g_door[BATCH];
__device__ float g_partial[BATCH*NCHUNK];

// ---------------------------------------------------------------
__global__ void zero_kernel(float4* __restrict__ p, long long n4) {
    long long i = (long long)blockIdx.x*blockDim.x + threadIdx.x;
    long long stride = (long long)gridDim.x*blockDim.x;
    float4 z = make_float4(0.f,0.f,0.f,0.f);
    for (; i < n4; i += stride) p[i] = z;
}

__global__ void seed_kernel(const int* __restrict__ start, float* __restrict__ R) {
    int b = threadIdx.x;
    if (b < BATCH) {
        int r = start[2*b], c = start[2*b+1];
        R[(size_t)b*HW + (size_t)r*WW + c] = 1.0f;
        g_keys[b] = 0.0f;
        for (int j = 0; j < NCHUNK; ++j) g_partial[b*NCHUNK + j] = 0.0f;
    }
}

// keys += sum(partials); zero partials; door_pass = sigmoid(kg*(keys-1))
__global__ void door_kernel(const float* __restrict__ kg) {
    int b = threadIdx.x;
    if (b < BATCH) {
        float s = 0.0f;
        for (int j = 0; j < NCHUNK; ++j) {
            s += g_partial[b*NCHUNK + j];
            g_partial[b*NCHUNK + j] = 0.0f;
        }
        g_keys[b] += s;
        float x = kg[0] * (g_keys[b] - 1.0f);
        g_door[b] = 1.0f / (1.0f + expf(-x));
    }
}

// walk = 0.25 * floor * (1 - locked + locked*door_pass)   (0.25 folded in)
__global__ void walk_kernel(const float4* __restrict__ fl,
                            const float4* __restrict__ lk,
                            float4* __restrict__ wk) {
    int b = blockIdx.y;
    float dp = g_door[b];
    size_t base = (size_t)b * (HW/4);
    int i = blockIdx.x*blockDim.x + threadIdx.x;
    int stride = gridDim.x*blockDim.x;
    for (; i < HW/4; i += stride) {
        float4 f = fl[base + i];
        float4 l = lk[base + i];
        float4 w;
        w.x = 0.25f * f.x * (1.0f - l.x + l.x*dp);
        w.y = 0.25f * f.y * (1.0f - l.y + l.y*dp);
        w.z = 0.25f * f.z * (1.0f - l.z + l.z*dp);
        w.w = 0.25f * f.w * (1.0f - l.w + l.w*dp);
        wk[base + i] = w;
    }
}

// fused 5-iteration Jacobi stencil. 64x64 tile, halo 5, walk held in registers,
// 4 CTAs/SM. Local layout: x = gx - tx0 + 8 (all gmem float4 accesses aligned).
__global__ __launch_bounds__(256, 4)
void stencil_kernel(const float* __restrict__ Rin,
                    const float4* __restrict__ walk4,
                    float* __restrict__ Rout) {
    extern __shared__ float sm[];
    float* Rs0 = sm;                 // ROWS*STR floats
    float* Rs1 = sm + ROWS*STR;

    const int b   = blockIdx.z;
    const int ty0 = blockIdx.y * TILE;
    const int tx0 = blockIdx.x * TILE;
    const int tid = threadIdx.x;

    const float4* __restrict__ Rb4 = (const float4*)(Rin + (size_t)b*HW);
    const float4* __restrict__ Wb4 = walk4 + (size_t)b*(HW/4);
    const int cxf4 = (tx0 - 8) / 4;  // f4 column base offset (can be negative)

    // ---- load R tile (float4, per-f4 fully in/out of image), zero Rs1 ----
    float4* Rs04 = (float4*)Rs0;
    float4* Rs14 = (float4*)Rs1;
    const float4 z4 = make_float4(0.f,0.f,0.f,0.f);
    for (int idx = tid; idx < ROWS*VPRX; idx += 256) {
        int y = idx / VPRX, v = idx - y*VPRX;
        int gy = ty0 + y - KFUSE;
        int gx = tx0 + 4*v - 8;
        float4 r = z4;
        if ((unsigned)gy < HH && (unsigned)gx < WW)
            r = __ldg(Rb4 + (size_t)gy*W4R + (cxf4 + v));
        Rs04[idx] = r;
        Rs14[idx] = z4;              // frame cells of nxt must be zero
    }

    // ---- thread -> (column v, row group g); walk into registers ----
    int v = 1 + (tid % NCOL);        // 1..18
    int g = tid / NCOL;              // 0..14
    const bool act = (g < NG);       // 216 active threads
    if (!act) { v = 1; g = 0; }
    const int y0 = 1 + g*RPG;        // rows y0..y0+5 in [1,72]

    float4 Wr[RPG];
    #pragma unroll
    for (int i = 0; i < RPG; ++i) {
        int gy = ty0 + (y0 + i) - KFUSE;
        int gx = tx0 + 4*v - 8;
        Wr[i] = z4;
        if ((unsigned)gy < HH && (unsigned)gx < WW)
            Wr[i] = __ldg(Wb4 + (size_t)gy*W4R + (cxf4 + v));
    }
    __syncthreads();

    float4* Ro4 = (float4*)(Rout + (size_t)b*HW);

    float* cur = Rs0;
    float* nxt = Rs1;
    #pragma unroll
    for (int it = 0; it < KFUSE; ++it) {
        const float4* __restrict__ c4 = (const float4*)cur;
        float4* __restrict__ n4p = (float4*)nxt;
        const bool last = (it == KFUSE-1);

        float4 U = c4[(y0-1)*VPRX + v];
        float4 C = c4[ y0   *VPRX + v];
        #pragma unroll
        for (int i = 0; i < RPG; ++i) {
            const int y = y0 + i;
            float4 D = c4[(y+1)*VPRX + v];
            float  L = cur[y*STR + 4*v - 1];
            float  R = cur[y*STR + 4*v + 4];
            float4 W = Wr[i];
            float4 o;
            o.x = fminf(fmaf((U.x+D.x)+(L  +C.y), W.x, C.x), 1.0f);
            o.y = fminf(fmaf((U.y+D.y)+(C.x+C.z), W.y, C.y), 1.0f);
            o.z = fminf(fmaf((U.z+D.z)+(C.y+C.w), W.z, C.z), 1.0f);
            o.w = fminf(fmaf((U.w+D.w)+(C.z+R  ), W.w, C.w), 1.0f);
            if (!last) {
                if (act) n4p[y*VPRX + v] = o;
            } else {
                // stream interior (v in [2,17], y in [5,68]) straight to gmem
                if (act && v >= 2 && v <= 17 && y >= KFUSE && y <= ROWS-1-KFUSE) {
                    int gy = ty0 + y - KFUSE;
                    Ro4[(size_t)gy*W4R + (cxf4 + v)] = o;
                }
            }
            U = C; C = D;
        }
        __syncthreads();
        float* t = cur; cur = nxt; nxt = t;
    }
}

// partial[b][chunk] = sum(R*key_loc) over chunk (deterministic)
__global__ void reduce_kernel(const float* __restrict__ R,
                              const float* __restrict__ keyloc) {
    int b = blockIdx.y;
    int chunk = blockIdx.x;
    const int per = HW/4/NCHUNK;            // 8192 float4
    const float4* r4 = (const float4*)(R      + (size_t)b*HW) + chunk*per;
    const float4* k4 = (const float4*)(keyloc + (size_t)b*HW) + chunk*per;
    float acc = 0.0f;
    for (int i = threadIdx.x; i < per; i += blockDim.x) {
        float4 r = r4[i], k = k4[i];
        acc += (r.x*k.x + r.y*k.y) + (r.z*k.z + r.w*k.w);
    }
    __shared__ float sred[256];
    sred[threadIdx.x] = acc;
    __syncthreads();
    for (int s = 128; s > 0; s >>= 1) {
        if (threadIdx.x < s) sred[threadIdx.x] += sred[threadIdx.x + s];
        __syncthreads();
    }
    if (threadIdx.x == 0) g_partial[b*NCHUNK + chunk] = sred[0];
}

// out[b] = R[b, clip(goal_r), clip(goal_c)]
__global__ void gather_kernel(const float* __restrict__ R,
                              const int* __restrict__ goal,
                              float* __restrict__ out) {
    int b = threadIdx.x;
    if (b < BATCH) {
        int gr = min(max(goal[2*b],   0), HH-1);
        int gc = min(max(goal[2*b+1], 0), WW-1);
        out[b] = R[(size_t)b*HW + (size_t)gr*WW + gc];
    }
}

// ---------------------------------------------------------------
extern "C" void kernel_launch(void* const* d_in, const int* in_sizes, int n_in,
                              void* d_out, int out_size) {
    const float* floor_  = (const float*)d_in[0];
    const float* keyloc  = (const float*)d_in[1];
    const float* locked  = (const float*)d_in[2];
    const int*   start   = (const int*)  d_in[3];
    const int*   goal    = (const int*)  d_in[4];
    const float* keygate = (const float*)d_in[5];
    float* out = (float*)d_out;

    float *RA, *RB, *Wp;
    cudaGetSymbolAddress((void**)&RA, g_RA);
    cudaGetSymbolAddress((void**)&RB, g_RB);
    cudaGetSymbolAddress((void**)&Wp, g_walk);

    cudaFuncSetAttribute(stencil_kernel,
                         cudaFuncAttributeMaxDynamicSharedMemorySize, SMEM_BYTES);

    zero_kernel<<<4096, 256>>>((float4*)RA, (long long)BATCH*HW/4);
    seed_kernel<<<1, 128>>>(start, RA);

    float* cur = RA;
    float* oth = RB;
    for (int stage = 0; stage < 3; ++stage) {
        door_kernel<<<1, 128>>>(keygate);   // folds in previous stage's partial sums
        walk_kernel<<<dim3(32, BATCH), 256>>>((const float4*)floor_,
                                              (const float4*)locked,
                                              (float4*)Wp);
        for (int ss = 0; ss < 3; ++ss) {    // 3 super-steps x 5 fused iters = 15
            stencil_kernel<<<dim3(WW/TILE, HH/TILE, BATCH), 256, SMEM_BYTES>>>(
                cur, (const float4*)Wp, oth);
            float* t = cur; cur = oth; oth = t;
        }
        if (stage < 2)                      // last stage's key update is dead code
            reduce_kernel<<<dim3(NCHUNK, BATCH), 256>>>(cur, keyloc);
    }
    gather_kernel<<<1, 128>>>(cur, goal, out);
}